// round 14
// baseline (speedup 1.0000x reference)
#include <cuda_runtime.h>
#include <cuda_bf16.h>
#include <math_constants.h>

#define N_TOK  16384
#define DIMK   256
#define NCTA   148
#define NUNITS 1024            // 128 rowblocks x 8 column chunks (16 tiles each)
#define RSTRIDE 528u
#define TILE_B (128u * RSTRIDE)
#define SMEM_DYN (3u * TILE_B)

__device__ __align__(16) __nv_bfloat16 g_bf[2][N_TOK * DIMK];
__device__ float2 g_cp[256 * N_TOK];       // per (rowblock, warp-half, col) partial
__device__ float2 g_rpu[NUNITS * 128];     // per (unit, local row) partial (run-final or neutral)
__device__ float  g_diag[N_TOK];
__device__ float  g_rowloss[2 * N_TOK];

__device__ __forceinline__ unsigned smem_u32(const void* p) {
    unsigned a;
    asm("{ .reg .u64 t; cvta.to.shared.u64 t, %1; cvt.u32.u64 %0, t; }" : "=r"(a) : "l"(p));
    return a;
}
__device__ __forceinline__ unsigned bf16x2_pack(float lo, float hi) {
    unsigned r;
    asm("cvt.rn.bf16x2.f32 %0, %1, %2;" : "=r"(r) : "f"(hi), "f"(lo));
    return r;
}
__device__ __forceinline__ float ex2f(float x) {
    float y; asm("ex2.approx.ftz.f32 %0, %1;" : "=f"(y) : "f"(x)); return y;
}
// MUFU-based exp-sum (row path; mostly skipped).
__device__ __forceinline__ float expsum8_m(const float* v, float k2, float base) {
    float s0 = 0.f, s1 = 0.f;
#pragma unroll
    for (int i = 0; i < 8; i += 2) {
        s0 += ex2f(fmaf(v[i],     k2, -base));
        s1 += ex2f(fmaf(v[i + 1], k2, -base));
    }
    return s0 + s1;
}

// ---- packed f32x2 exp2 (fma pipe; col path) ----
__device__ __forceinline__ unsigned long long pk2(float lo, float hi) {
    unsigned long long r;
    asm("mov.b64 %0, {%1, %2};" : "=l"(r) : "f"(lo), "f"(hi));
    return r;
}
__device__ __forceinline__ unsigned long long add2(unsigned long long a, unsigned long long b) {
    unsigned long long d;
    asm("add.rn.f32x2 %0, %1, %2;" : "=l"(d) : "l"(a), "l"(b));
    return d;
}
__device__ __forceinline__ unsigned long long fma2v(unsigned long long a, unsigned long long b,
                                                    unsigned long long c) {
    unsigned long long d;
    asm("fma.rn.f32x2 %0, %1, %2, %3;" : "=l"(d) : "l"(a), "l"(b), "l"(c));
    return d;
}
__device__ __forceinline__ unsigned long long exp2_2(unsigned long long y2) {
    const unsigned long long M2  = pk2(12582912.0f, 12582912.0f);
    const unsigned long long NM2 = pk2(-12582912.0f, -12582912.0f);
    const unsigned long long N1  = pk2(-1.0f, -1.0f);
    const unsigned long long C4  = pk2(0.00961812911f, 0.00961812911f);
    const unsigned long long C3  = pk2(0.0555041087f, 0.0555041087f);
    const unsigned long long C2  = pk2(0.240226507f, 0.240226507f);
    const unsigned long long C1  = pk2(0.69314718f, 0.69314718f);
    const unsigned long long ONE = pk2(1.0f, 1.0f);
    unsigned long long t2 = add2(y2, M2);
    unsigned long long u2 = add2(t2, NM2);
    unsigned long long f2 = fma2v(u2, N1, y2);
    unsigned long long p2 = fma2v(C4, f2, C3);
    p2 = fma2v(p2, f2, C2);
    p2 = fma2v(p2, f2, C1);
    p2 = fma2v(p2, f2, ONE);
    unsigned tlo, thi, plo, phi;
    asm("mov.b64 {%0, %1}, %2;" : "=r"(tlo), "=r"(thi) : "l"(t2));
    asm("mov.b64 {%0, %1}, %2;" : "=r"(plo), "=r"(phi) : "l"(p2));
    unsigned rlo = plo + (tlo << 23);
    unsigned rhi = phi + (thi << 23);
    unsigned long long r;
    asm("mov.b64 %0, {%1, %2};" : "=l"(r) : "r"(rlo), "r"(rhi));
    return r;
}
// fma-pipe exp-sum of 8 (col path; args <= 0 after base subtraction).
__device__ __forceinline__ float expsum8_f(const float* v, float k2, float base) {
    float y[8];
#pragma unroll
    for (int i = 0; i < 8; ++i) y[i] = fmaxf(fmaf(v[i], k2, -base), -120.0f);
    unsigned long long s2 = exp2_2(pk2(y[0], y[1]));
    s2 = add2(s2, exp2_2(pk2(y[2], y[3])));
    s2 = add2(s2, exp2_2(pk2(y[4], y[5])));
    s2 = add2(s2, exp2_2(pk2(y[6], y[7])));
    float lo, hi;
    asm("mov.b64 {%0, %1}, %2;" : "=f"(lo), "=f"(hi) : "l"(s2));
    return lo + hi;
}

#define MBARRIER_INIT(a, c) \
    asm volatile("mbarrier.init.shared.b64 [%0], %1;" :: "r"((unsigned)(a)), "r"((unsigned)(c)) : "memory")
#define MBARRIER_ARRIVE(a) \
    asm volatile("mbarrier.arrive.shared.b64 _, [%0];" :: "r"((unsigned)(a)) : "memory")
#define MBARRIER_WAIT(a, par) do { \
    unsigned _m = (unsigned)(a), _p = (unsigned)(par), _d; \
    asm volatile("{ .reg .pred p; mbarrier.try_wait.parity.acquire.cta.shared::cta.b64 p, [%1], %2; selp.b32 %0,1,0,p; }" \
        : "=r"(_d) : "r"(_m), "r"(_p) : "memory"); \
    if (!_d) asm volatile("{ .reg .pred P; WL_%=: mbarrier.try_wait.parity.acquire.cta.shared::cta.b64 P, [%0], %1, 0x989680; @P bra.uni WD_%=; bra.uni WL_%=; WD_%=: }" \
        :: "r"(_m), "r"(_p) : "memory"); \
} while (0)

#define STS128(r0, r1, r2, r3, a) \
    asm volatile("st.shared.v4.b32 [%0], {%1,%2,%3,%4};" :: "r"((unsigned)(a)), "r"(r0), "r"(r1), "r"(r2), "r"(r3) : "memory")
#define BAR_SYNC(id, n) asm volatile("bar.sync %0, %1;" :: "r"(id), "r"(n) : "memory")

#define LDSM_X4(d, a) \
    asm volatile("ldmatrix.sync.aligned.m8n8.x4.shared.b16 {%0,%1,%2,%3}, [%4];" \
        : "=r"((d)[0]), "=r"((d)[1]), "=r"((d)[2]), "=r"((d)[3]) : "r"((unsigned)(a)))
#define LDSM_X4T(d, a) \
    asm volatile("ldmatrix.sync.aligned.m8n8.x4.trans.shared.b16 {%0,%1,%2,%3}, [%4];" \
        : "=r"((d)[0]), "=r"((d)[1]), "=r"((d)[2]), "=r"((d)[3]) : "r"((unsigned)(a)))

#define MMA16816(d, a, b0, b1) \
    asm volatile("mma.sync.aligned.m16n8k16.row.col.f32.bf16.bf16.f32 " \
        "{%0,%1,%2,%3}, {%4,%5,%6,%7}, {%8,%9}, {%0,%1,%2,%3};" \
        : "+f"((d)[0]), "+f"((d)[1]), "+f"((d)[2]), "+f"((d)[3]) \
        : "r"((a)[0]), "r"((a)[1]), "r"((a)[2]), "r"((a)[3]), "r"(b0), "r"(b1))

__device__ __forceinline__ void fill_tile(unsigned sbase, const uint4* __restrict__ src,
                                          int t0, int stride) {
#pragma unroll 4
    for (int idx = t0; idx < 4096; idx += stride) {
        uint4 v = src[idx];
        STS128(v.x, v.y, v.z, v.w,
               sbase + (unsigned)(idx >> 5) * RSTRIDE + (unsigned)(idx & 31) * 16u);
    }
}

__global__ void __launch_bounds__(512) convert_bf16(const float* __restrict__ img,
                                                    const float* __restrict__ txt)
{
    unsigned t = blockIdx.x * 512u + threadIdx.x;
    const float* src = (t >> 20) ? txt : img;
    __nv_bfloat16* dst = g_bf[t >> 20];
    unsigned i = (t & 0xFFFFFu) << 2;
    float4 v = *(const float4*)(src + i);
    *(uint2*)(dst + i) = make_uint2(bf16x2_pack(v.x, v.y), bf16x2_pack(v.z, v.w));
}

// Persistent: 148 CTAs, static unit ranges. Unit = (rowblock rb = u>>3, chunk = u&7).
__global__ void __launch_bounds__(512, 1)
clip_main(const float* __restrict__ scale_ptr)
{
    extern __shared__ char dsm[];
    __shared__ __align__(8) unsigned long long sh_bar[4];
    __shared__ float sm_m[512], sm_s[512], sm_p[128];

    const int tid = threadIdx.x, wid = tid >> 5, lane = tid & 31;
    const int cta = blockIdx.x;
    const int u0 = (cta * NUNITS) / NCTA;
    const int u1 = ((cta + 1) * NUNITS) / NCTA;

    const unsigned abase = smem_u32(dsm);
    const unsigned bb[2] = { abase + TILE_B, abase + 2u * TILE_B };
    const unsigned smbar = smem_u32(sh_bar);

    if (tid == 0) {
        MBARRIER_INIT(smbar + 0, 256);  MBARRIER_INIT(smbar + 8, 256);
        MBARRIER_INIT(smbar + 16, 256); MBARRIER_INIT(smbar + 24, 256);
    }
    __syncthreads();

    const float scale = *scale_ptr;
    const float k2 = scale * 1.4426950408889634f;

    if (wid >= 8) {
        // ---------- Loaders ----------
        const int ltid = tid - 256;
        const uint4* bsrc = (const uint4*)g_bf[1];
        int c = 0, ph[2] = {0, 0};
        for (int u = u0; u < u1; ++u) {
            const int chunk = u & 7;
            for (int t = 0; t < 16; ++t, ++c) {
                const int b = c & 1;
                if (c >= 2) { MBARRIER_WAIT(smbar + 16 + (b << 3), ph[b]); ph[b] ^= 1; }
                fill_tile(bb[b], bsrc + (size_t)(chunk * 16 + t) * 4096, ltid, 256);
                MBARRIER_ARRIVE(smbar + (b << 3));
            }
        }
    } else {
        // ---------- Compute warps ----------
        const int wx = wid & 1, wy = wid >> 1;
        unsigned aAddr[4];
#pragma unroll
        for (int mt = 0; mt < 4; ++mt) {
            unsigned row = (unsigned)(wx * 64 + mt * 16 + (lane & 7) + ((lane >> 3) & 1) * 8);
            aAddr[mt] = abase + row * RSTRIDE + (unsigned)(lane >> 4) * 16u;
        }
        unsigned bOff[2];
#pragma unroll
        for (int nt2 = 0; nt2 < 2; ++nt2) {
            unsigned row = (unsigned)(wy * 32 + nt2 * 16 + (lane & 7) + ((lane >> 4) & 1) * 8);
            bOff[nt2] = row * RSTRIDE + (unsigned)((lane >> 3) & 1) * 16u;
        }

        float mst[8], sst[8];
#pragma unroll
        for (int i = 0; i < 8; ++i) { mst[i] = -1e30f; sst[i] = 0.0f; }

        int c = 0, ph[2] = {0, 0}, prev_rb = -1, run_u0 = u0;

        for (int u = u0; u < u1; ++u) {
            const int rb = u >> 3, chunk = u & 7;
            const int rowBase = rb << 7;
            if (rb != prev_rb) {
                if (prev_rb >= 0) {
                    if ((lane & 3) == 0) {
#pragma unroll
                        for (int mt = 0; mt < 4; ++mt)
#pragma unroll
                            for (int h = 0; h < 2; ++h) {
                                const int row = wx * 64 + mt * 16 + (lane >> 2) + 8 * h;
                                sm_m[wy * 128 + row] = mst[mt * 2 + h];
                                sm_s[wy * 128 + row] = sst[mt * 2 + h];
                            }
                    }
                    BAR_SYNC(1, 256);
                    if (tid < 128) {
                        float mM = sm_m[tid];
#pragma unroll
                        for (int q = 1; q < 4; ++q) mM = fmaxf(mM, sm_m[q * 128 + tid]);
                        float sM = 0.0f;
#pragma unroll
                        for (int q = 0; q < 4; ++q)
                            sM += sm_s[q * 128 + tid] * ex2f(k2 * (sm_m[q * 128 + tid] - mM));
                        g_rpu[(size_t)(u - 1) * 128 + tid] = make_float2(mM, sM);
                        const float2 neutral = make_float2(-1e30f, 0.0f);
                        for (int uu = run_u0; uu < u - 1; ++uu)
                            g_rpu[(size_t)uu * 128 + tid] = neutral;
                        const int dchunk = prev_rb >> 4;
                        const int clo = run_u0 - (prev_rb << 3), chi = u - (prev_rb << 3);
                        if (dchunk >= clo && dchunk < chi)
                            g_diag[(prev_rb << 7) + tid] = sm_p[tid];
                    }
                    BAR_SYNC(1, 256);
#pragma unroll
                    for (int i = 0; i < 8; ++i) { mst[i] = -1e30f; sst[i] = 0.0f; }
                    run_u0 = u;
                }
                fill_tile(abase, (const uint4*)(g_bf[0] + (size_t)rowBase * DIMK), tid, 256);
                BAR_SYNC(1, 256);
                prev_rb = rb;
            }

            for (int t = 0; t < 16; ++t, ++c) {
                const int b = c & 1;
                const int jj = chunk * 16 + t;
                MBARRIER_WAIT(smbar + (b << 3), ph[b]); ph[b] ^= 1;
                const unsigned bbase = bb[b];

                float acc[4][4][4];
#pragma unroll
                for (int mt = 0; mt < 4; ++mt)
#pragma unroll
                    for (int nt = 0; nt < 4; ++nt)
#pragma unroll
                        for (int e = 0; e < 4; ++e) acc[mt][nt][e] = 0.0f;

#pragma unroll 4
                for (int ks = 0; ks < 16; ++ks) {
                    const unsigned ko = (unsigned)ks * 32u;
                    unsigned a[4][4];
#pragma unroll
                    for (int mt = 0; mt < 4; ++mt) LDSM_X4(a[mt], aAddr[mt] + ko);
#pragma unroll
                    for (int nt2 = 0; nt2 < 2; ++nt2) {
                        unsigned bf[4];
                        LDSM_X4T(bf, bbase + bOff[nt2] + ko);
#pragma unroll
                        for (int mt = 0; mt < 4; ++mt) {
                            MMA16816(acc[mt][nt2 * 2 + 0], a[mt], bf[0], bf[1]);
                            MMA16816(acc[mt][nt2 * 2 + 1], a[mt], bf[2], bf[3]);
                        }
                    }
                }
                MBARRIER_ARRIVE(smbar + 16 + (b << 3));

                // Column partial (fma-pipe exps, every tile)
                {
                    float cm[8], cs[8];
#pragma unroll
                    for (int nt = 0; nt < 4; ++nt)
#pragma unroll
                        for (int e = 0; e < 2; ++e) {
                            const int ci = nt * 2 + e;
                            float v0 = fmaxf(fmaxf(acc[0][nt][e], acc[0][nt][2 + e]),
                                             fmaxf(acc[1][nt][e], acc[1][nt][2 + e]));
                            float v1 = fmaxf(fmaxf(acc[2][nt][e], acc[2][nt][2 + e]),
                                             fmaxf(acc[3][nt][e], acc[3][nt][2 + e]));
                            cm[ci] = fmaxf(v0, v1);
                        }
#pragma unroll
                    for (int ci = 0; ci < 8; ++ci) {
                        cm[ci] = fmaxf(cm[ci], __shfl_xor_sync(0xffffffffu, cm[ci], 4));
                        cm[ci] = fmaxf(cm[ci], __shfl_xor_sync(0xffffffffu, cm[ci], 8));
                        cm[ci] = fmaxf(cm[ci], __shfl_xor_sync(0xffffffffu, cm[ci], 16));
                    }
#pragma unroll
                    for (int nt = 0; nt < 4; ++nt)
#pragma unroll
                        for (int e = 0; e < 2; ++e) {
                            const int ci = nt * 2 + e;
                            float v[8];
#pragma unroll
                            for (int mt = 0; mt < 4; ++mt) {
                                v[mt * 2 + 0] = acc[mt][nt][e];
                                v[mt * 2 + 1] = acc[mt][nt][2 + e];
                            }
                            cs[ci] = expsum8_f(v, k2, k2 * cm[ci]);
                        }
#pragma unroll
                    for (int ci = 0; ci < 8; ++ci) {
                        cs[ci] += __shfl_xor_sync(0xffffffffu, cs[ci], 4);
                        cs[ci] += __shfl_xor_sync(0xffffffffu, cs[ci], 8);
                        cs[ci] += __shfl_xor_sync(0xffffffffu, cs[ci], 16);
                    }
                    if (lane < 4) {
#pragma unroll
                        for (int nt = 0; nt < 4; ++nt)
#pragma unroll
                            for (int e = 0; e < 2; ++e) {
                                const int ci = nt * 2 + e;
                                const int cg = jj * 128 + wy * 32 + nt * 8 + 2 * lane + e;
                                g_cp[(size_t)(rb * 2 + wx) * N_TOK + cg] = make_float2(cm[ci], cs[ci]);
                            }
                    }
                }

                // Row-direction online LSE (MUFU exps, mostly skipped)
#pragma unroll
                for (int mt = 0; mt < 4; ++mt)
#pragma unroll
                    for (int h = 0; h < 2; ++h) {
                        const int st = mt * 2 + h;
                        float v[8];
#pragma unroll
                        for (int nt = 0; nt < 4; ++nt) {
                            v[nt * 2 + 0] = acc[mt][nt][h * 2 + 0];
                            v[nt * 2 + 1] = acc[mt][nt][h * 2 + 1];
                        }
                        if (jj == rb) {
                            const int row = wx * 64 + mt * 16 + (lane >> 2) + 8 * h;
#pragma unroll
                            for (int nt = 0; nt < 4; ++nt)
#pragma unroll
                                for (int e = 0; e < 2; ++e) {
                                    const int col = wy * 32 + nt * 8 + 2 * (lane & 3) + e;
                                    if (col == row) sm_p[row] = v[nt * 2 + e];
                                }
                        }
                        float vm = v[0];
#pragma unroll
                        for (int i = 1; i < 8; ++i) vm = fmaxf(vm, v[i]);
                        vm = fmaxf(vm, __shfl_xor_sync(0xffffffffu, vm, 1));
                        vm = fmaxf(vm, __shfl_xor_sync(0xffffffffu, vm, 2));
                        if (__all_sync(0xffffffffu, vm < mst[st] - 2.0f)) continue;
                        const float mnew = fmaxf(mst[st], vm);
                        const float base = k2 * mnew;
                        float sum = expsum8_m(v, k2, base);
                        sum += __shfl_xor_sync(0xffffffffu, sum, 1);
                        sum += __shfl_xor_sync(0xffffffffu, sum, 2);
                        sst[st] = fmaf(sst[st], ex2f(fmaf(mst[st], k2, -base)), sum);
                        mst[st] = mnew;
                    }
            }
        }

        // ---- finalize last run ----
        if ((lane & 3) == 0) {
#pragma unroll
            for (int mt = 0; mt < 4; ++mt)
#pragma unroll
                for (int h = 0; h < 2; ++h) {
                    const int row = wx * 64 + mt * 16 + (lane >> 2) + 8 * h;
                    sm_m[wy * 128 + row] = mst[mt * 2 + h];
                    sm_s[wy * 128 + row] = sst[mt * 2 + h];
                }
        }
        BAR_SYNC(1, 256);
        if (tid < 128) {
            float mM = sm_m[tid];
#pragma unroll
            for (int q = 1; q < 4; ++q) mM = fmaxf(mM, sm_m[q * 128 + tid]);
            float sM = 0.0f;
#pragma unroll
            for (int q = 0; q < 4; ++q)
                sM += sm_s[q * 128 + tid] * ex2f(k2 * (sm_m[q * 128 + tid] - mM));
            g_rpu[(size_t)(u1 - 1) * 128 + tid] = make_float2(mM, sM);
            const float2 neutral = make_float2(-1e30f, 0.0f);
            for (int uu = run_u0; uu < u1 - 1; ++uu)
                g_rpu[(size_t)uu * 128 + tid] = neutral;
            const int dchunk = prev_rb >> 4;
            const int clo = run_u0 - (prev_rb << 3), chi = u1 - (prev_rb << 3);
            if (dchunk >= clo && dchunk < chi)
                g_diag[(prev_rb << 7) + tid] = sm_p[tid];
        }
        BAR_SYNC(1, 256);
    }
}

__global__ void __launch_bounds__(256) clip_colred(const float* __restrict__ scale_ptr)
{
    const float scale = *scale_ptr;
    const float k2 = scale * 1.4426950408889634f;
    const int c = blockIdx.x * 256 + threadIdx.x;

    float M = -CUDART_INF_F;
#pragma unroll 4
    for (int i = 0; i < 256; ++i) M = fmaxf(M, g_cp[(size_t)i * N_TOK + c].x);
    float S = 0.0f;
#pragma unroll 4
    for (int i = 0; i < 256; ++i) {
        float2 p = g_cp[(size_t)i * N_TOK + c];
        S += p.y * ex2f(k2 * (p.x - M));
    }
    const float d = scale * g_diag[c];
    g_rowloss[N_TOK + c] = 0.69314718055994531f * fmaf(k2, M, __log2f(S)) - d;

    const int rb = c >> 7, lr = c & 127;
    float mM = -CUDART_INF_F;
#pragma unroll
    for (int k = 0; k < 8; ++k) mM = fmaxf(mM, g_rpu[(size_t)(rb * 8 + k) * 128 + lr].x);
    float sM = 0.0f;
#pragma unroll
    for (int k = 0; k < 8; ++k) {
        float2 p = g_rpu[(size_t)(rb * 8 + k) * 128 + lr];
        sM += p.y * ex2f(k2 * (p.x - mM));
    }
    g_rowloss[c] = 0.69314718055994531f * fmaf(k2, mM, __log2f(sM)) - d;
}

__global__ void __launch_bounds__(1024) clip_reduce(float* __restrict__ out)
{
    __shared__ float sm[1024];
    float a = 0.0f;
    const float4* p = (const float4*)g_rowloss;
#pragma unroll 4
    for (int i = threadIdx.x; i < 8192; i += 1024) {
        float4 v = p[i];
        a += (v.x + v.y) + (v.z + v.w);
    }
    sm[threadIdx.x] = a;
    __syncthreads();
    for (int st = 512; st > 0; st >>= 1) {
        if (threadIdx.x < st) sm[threadIdx.x] += sm[threadIdx.x + st];
        __syncthreads();
    }
    if (threadIdx.x == 0) out[0] = sm[0] * (1.0f / 32768.0f);
}

extern "C" void kernel_launch(void* const* d_in, const int* in_sizes, int n_in,
                              void* d_out, int out_size)
{
    (void)in_sizes; (void)n_in; (void)out_size;
    const float* img = (const float*)d_in[0];
    const float* txt = (const float*)d_in[1];
    const float* scl = (const float*)d_in[2];

    cudaFuncSetAttribute(clip_main, cudaFuncAttributeMaxDynamicSharedMemorySize, SMEM_DYN);
    convert_bf16<<<4096, 512>>>(img, txt);
    clip_main<<<NCTA, 512, SMEM_DYN>>>(scl);
    clip_colred<<<64, 256>>>(scl);
    clip_reduce<<<1, 1024>>>((float*)d_out);
}

// round 15
// speedup vs baseline: 1.2211x; 1.2211x over previous
#include <cuda_runtime.h>
#include <cuda_bf16.h>
#include <math_constants.h>

#define N_TOK  16384
#define DIMK   256
#define NCTA   148
#define NUNITS 1024            // 128 rowblocks x 8 column chunks (16 tiles each)
#define RSTRIDE 528u           // padded row: 512B data + 16B pad (conflict-free LDSM)
#define TILE_BYTES (128u * RSTRIDE)   // 67584, one contiguous tile in gmem AND smem
#define SMEM_DYN (3u * TILE_BYTES)

__device__ __align__(16) unsigned char g_bfp[2][(size_t)N_TOK * RSTRIDE];
__device__ float2 g_cp[256 * N_TOK];
__device__ float2 g_rpu[NUNITS * 128];
__device__ float  g_diag[N_TOK];
__device__ float  g_rowloss[2 * N_TOK];

__device__ __forceinline__ unsigned smem_u32(const void* p) {
    unsigned a;
    asm("{ .reg .u64 t; cvta.to.shared.u64 t, %1; cvt.u32.u64 %0, t; }" : "=r"(a) : "l"(p));
    return a;
}
__device__ __forceinline__ unsigned bf16x2_pack(float lo, float hi) {
    unsigned r;
    asm("cvt.rn.bf16x2.f32 %0, %1, %2;" : "=r"(r) : "f"(hi), "f"(lo));
    return r;
}
__device__ __forceinline__ float ex2f(float x) {
    float y; asm("ex2.approx.ftz.f32 %0, %1;" : "=f"(y) : "f"(x)); return y;
}
__device__ __forceinline__ float expsum8_m(const float* v, float k2, float base) {
    float s0 = 0.f, s1 = 0.f;
#pragma unroll
    for (int i = 0; i < 8; i += 2) {
        s0 += ex2f(fmaf(v[i],     k2, -base));
        s1 += ex2f(fmaf(v[i + 1], k2, -base));
    }
    return s0 + s1;
}

#define MBARRIER_INIT(a, c) \
    asm volatile("mbarrier.init.shared.b64 [%0], %1;" :: "r"((unsigned)(a)), "r"((unsigned)(c)) : "memory")
#define MBARRIER_ARRIVE(a) \
    asm volatile("mbarrier.arrive.shared.b64 _, [%0];" :: "r"((unsigned)(a)) : "memory")
#define MBARRIER_EXPECT_TX(a, tx) \
    asm volatile("mbarrier.arrive.expect_tx.shared.b64 _, [%0], %1;" :: "r"((unsigned)(a)), "r"((unsigned)(tx)) : "memory")
#define MBARRIER_WAIT(a, par) do { \
    unsigned _m = (unsigned)(a), _p = (unsigned)(par), _d; \
    asm volatile("{ .reg .pred p; mbarrier.try_wait.parity.acquire.cta.shared::cta.b64 p, [%1], %2; selp.b32 %0,1,0,p; }" \
        : "=r"(_d) : "r"(_m), "r"(_p) : "memory"); \
    if (!_d) asm volatile("{ .reg .pred P; WL_%=: mbarrier.try_wait.parity.acquire.cta.shared::cta.b64 P, [%0], %1, 0x989680; @P bra.uni WD_%=; bra.uni WL_%=; WD_%=: }" \
        :: "r"(_m), "r"(_p) : "memory"); \
} while (0)
#define CP_BULK(dst, src, sz, mbar) \
    asm volatile("cp.async.bulk.shared::cluster.global.mbarrier::complete_tx::bytes [%0], [%1], %2, [%3];" \
        :: "r"((unsigned)(dst)), "l"(src), "r"((unsigned)(sz)), "r"((unsigned)(mbar)) : "memory")

#define LDSM_X4(d, a) \
    asm volatile("ldmatrix.sync.aligned.m8n8.x4.shared.b16 {%0,%1,%2,%3}, [%4];" \
        : "=r"((d)[0]), "=r"((d)[1]), "=r"((d)[2]), "=r"((d)[3]) : "r"((unsigned)(a)))
#define LDSM_X4T(d, a) \
    asm volatile("ldmatrix.sync.aligned.m8n8.x4.trans.shared.b16 {%0,%1,%2,%3}, [%4];" \
        : "=r"((d)[0]), "=r"((d)[1]), "=r"((d)[2]), "=r"((d)[3]) : "r"((unsigned)(a)))

#define MMA16816(d, a, b0, b1) \
    asm volatile("mma.sync.aligned.m16n8k16.row.col.f32.bf16.bf16.f32 " \
        "{%0,%1,%2,%3}, {%4,%5,%6,%7}, {%8,%9}, {%0,%1,%2,%3};" \
        : "+f"((d)[0]), "+f"((d)[1]), "+f"((d)[2]), "+f"((d)[3]) \
        : "r"((a)[0]), "r"((a)[1]), "r"((a)[2]), "r"((a)[3]), "r"(b0), "r"(b1))

// fp32 -> bf16, writing the padded-row (528B) gmem layout so tiles are contiguous.
__global__ void __launch_bounds__(512) convert_bf16(const float* __restrict__ img,
                                                    const float* __restrict__ txt)
{
    unsigned t = blockIdx.x * 512u + threadIdx.x;   // 2^21 threads, 4 floats each
    const float* src = (t >> 20) ? txt : img;
    unsigned char* dst = g_bfp[t >> 20];
    unsigned i = (t & 0xFFFFFu) << 2;               // element index
    unsigned row = i >> 8, col = i & 255u;
    float4 v = *(const float4*)(src + i);
    *(uint2*)(dst + (size_t)row * RSTRIDE + col * 2u) =
        make_uint2(bf16x2_pack(v.x, v.y), bf16x2_pack(v.z, v.w));
}

// Persistent: 148 CTAs x 256 threads (8 compute warps). B tiles arrive via
// cp.async.bulk issued by thread 0; no loader warps.
// bars: fullB0 @+0, fullB1 @+8 (tx) ; emptyB0 @+16, emptyB1 @+24 (cnt 256) ; fullA @+32 (tx)
__global__ void __launch_bounds__(256, 1)
clip_main(const float* __restrict__ scale_ptr)
{
    extern __shared__ __align__(16) char dsm[];
    __shared__ __align__(8) unsigned long long sh_bar[5];
    __shared__ float sm_m[512], sm_s[512], sm_p[128];

    const int tid = threadIdx.x, wid = tid >> 5, lane = tid & 31;
    const int cta = blockIdx.x;
    const int u0 = (cta * NUNITS) / NCTA;
    const int u1 = ((cta + 1) * NUNITS) / NCTA;
    const int ntile = (u1 - u0) * 16;

    const unsigned abase = smem_u32(dsm);
    const unsigned bb[2] = { abase + TILE_BYTES, abase + 2u * TILE_BYTES };
    const unsigned smbar = smem_u32(sh_bar);

    if (tid == 0) {
        MBARRIER_INIT(smbar + 0, 1);    MBARRIER_INIT(smbar + 8, 1);
        MBARRIER_INIT(smbar + 16, 256); MBARRIER_INIT(smbar + 24, 256);
        MBARRIER_INIT(smbar + 32, 1);
    }
    __syncthreads();

    const float scale = *scale_ptr;
    const float k2 = scale * 1.4426950408889634f;

    // Prime the first two B tiles.
    if (tid == 0) {
#pragma unroll
        for (int cpr = 0; cpr < 2; ++cpr) {
            const int uu = u0 + cpr / 16;
            const int jj = ((uu & 7) << 4) + (cpr & 15);
            MBARRIER_EXPECT_TX(smbar + (cpr << 3), TILE_BYTES);
            CP_BULK(bb[cpr], g_bfp[1] + (size_t)jj * TILE_BYTES, TILE_BYTES, smbar + (cpr << 3));
        }
    }

    const int wx = wid & 1, wy = wid >> 1;
    unsigned aAddr[4];
#pragma unroll
    for (int mt = 0; mt < 4; ++mt) {
        unsigned row = (unsigned)(wx * 64 + mt * 16 + (lane & 7) + ((lane >> 3) & 1) * 8);
        aAddr[mt] = abase + row * RSTRIDE + (unsigned)(lane >> 4) * 16u;
    }
    unsigned bOff[2];
#pragma unroll
    for (int nt2 = 0; nt2 < 2; ++nt2) {
        unsigned row = (unsigned)(wy * 32 + nt2 * 16 + (lane & 7) + ((lane >> 4) & 1) * 8);
        bOff[nt2] = row * RSTRIDE + (unsigned)((lane >> 3) & 1) * 16u;
    }

    float mst[8], sst[8];
#pragma unroll
    for (int i = 0; i < 8; ++i) { mst[i] = -1e30f; sst[i] = 0.0f; }

    int c = 0, pf[2] = {0, 0}, pe[2] = {0, 0}, pa = 0;
    int prev_rb = -1, run_u0 = u0;

    for (int u = u0; u < u1; ++u) {
        const int rb = u >> 3, chunk = u & 7;
        const int rowBase = rb << 7;
        if (rb != prev_rb) {
            if (prev_rb >= 0) {
                // ---- finalize run [run_u0, u) of prev_rb ----
                if ((lane & 3) == 0) {
#pragma unroll
                    for (int mt = 0; mt < 4; ++mt)
#pragma unroll
                        for (int h = 0; h < 2; ++h) {
                            const int row = wx * 64 + mt * 16 + (lane >> 2) + 8 * h;
                            sm_m[wy * 128 + row] = mst[mt * 2 + h];
                            sm_s[wy * 128 + row] = sst[mt * 2 + h];
                        }
                }
                __syncthreads();
                if (tid < 128) {
                    float mM = sm_m[tid];
#pragma unroll
                    for (int q = 1; q < 4; ++q) mM = fmaxf(mM, sm_m[q * 128 + tid]);
                    float sM = 0.0f;
#pragma unroll
                    for (int q = 0; q < 4; ++q)
                        sM += sm_s[q * 128 + tid] * ex2f(k2 * (sm_m[q * 128 + tid] - mM));
                    g_rpu[(size_t)(u - 1) * 128 + tid] = make_float2(mM, sM);
                    const float2 neutral = make_float2(-1e30f, 0.0f);
                    for (int uu = run_u0; uu < u - 1; ++uu)
                        g_rpu[(size_t)uu * 128 + tid] = neutral;
                    const int dchunk = prev_rb >> 4;
                    const int clo = run_u0 - (prev_rb << 3), chi = u - (prev_rb << 3);
                    if (dchunk >= clo && dchunk < chi)
                        g_diag[(prev_rb << 7) + tid] = sm_p[tid];
                }
                __syncthreads();
#pragma unroll
                for (int i = 0; i < 8; ++i) { mst[i] = -1e30f; sst[i] = 0.0f; }
                run_u0 = u;
            }
            // A tile bulk copy (all warps past old A due to syncthreads above /
            // or first iteration).
            __syncthreads();
            if (tid == 0) {
                MBARRIER_EXPECT_TX(smbar + 32, TILE_BYTES);
                CP_BULK(abase, g_bfp[0] + (size_t)rb * TILE_BYTES, TILE_BYTES, smbar + 32);
            }
            MBARRIER_WAIT(smbar + 32, pa); pa ^= 1;
            prev_rb = rb;
        }

        for (int t = 0; t < 16; ++t, ++c) {
            const int b = c & 1;
            const int jj = (chunk << 4) + t;
            MBARRIER_WAIT(smbar + (b << 3), pf[b]); pf[b] ^= 1;
            const unsigned bbase = bb[b];

            float acc[4][4][4];
#pragma unroll
            for (int mt = 0; mt < 4; ++mt)
#pragma unroll
                for (int nt = 0; nt < 4; ++nt)
#pragma unroll
                    for (int e = 0; e < 4; ++e) acc[mt][nt][e] = 0.0f;

#pragma unroll 4
            for (int ks = 0; ks < 16; ++ks) {
                const unsigned ko = (unsigned)ks * 32u;
                unsigned a[4][4];
#pragma unroll
                for (int mt = 0; mt < 4; ++mt) LDSM_X4(a[mt], aAddr[mt] + ko);
#pragma unroll
                for (int nt2 = 0; nt2 < 2; ++nt2) {
                    unsigned bf[4];
                    LDSM_X4T(bf, bbase + bOff[nt2] + ko);
#pragma unroll
                    for (int mt = 0; mt < 4; ++mt) {
                        MMA16816(acc[mt][nt2 * 2 + 0], a[mt], bf[0], bf[1]);
                        MMA16816(acc[mt][nt2 * 2 + 1], a[mt], bf[2], bf[3]);
                    }
                }
            }
            MBARRIER_ARRIVE(smbar + 16 + (b << 3));

            // Column partial over this warp's 64 rows
            {
                float cm[8], cs[8];
#pragma unroll
                for (int nt = 0; nt < 4; ++nt)
#pragma unroll
                    for (int e = 0; e < 2; ++e) {
                        const int ci = nt * 2 + e;
                        float v0 = fmaxf(fmaxf(acc[0][nt][e], acc[0][nt][2 + e]),
                                         fmaxf(acc[1][nt][e], acc[1][nt][2 + e]));
                        float v1 = fmaxf(fmaxf(acc[2][nt][e], acc[2][nt][2 + e]),
                                         fmaxf(acc[3][nt][e], acc[3][nt][2 + e]));
                        cm[ci] = fmaxf(v0, v1);
                    }
#pragma unroll
                for (int ci = 0; ci < 8; ++ci) {
                    cm[ci] = fmaxf(cm[ci], __shfl_xor_sync(0xffffffffu, cm[ci], 4));
                    cm[ci] = fmaxf(cm[ci], __shfl_xor_sync(0xffffffffu, cm[ci], 8));
                    cm[ci] = fmaxf(cm[ci], __shfl_xor_sync(0xffffffffu, cm[ci], 16));
                }
#pragma unroll
                for (int nt = 0; nt < 4; ++nt)
#pragma unroll
                    for (int e = 0; e < 2; ++e) {
                        const int ci = nt * 2 + e;
                        float v[8];
#pragma unroll
                        for (int mt = 0; mt < 4; ++mt) {
                            v[mt * 2 + 0] = acc[mt][nt][e];
                            v[mt * 2 + 1] = acc[mt][nt][2 + e];
                        }
                        cs[ci] = expsum8_m(v, k2, k2 * cm[ci]);
                    }
#pragma unroll
                for (int ci = 0; ci < 8; ++ci) {
                    cs[ci] += __shfl_xor_sync(0xffffffffu, cs[ci], 4);
                    cs[ci] += __shfl_xor_sync(0xffffffffu, cs[ci], 8);
                    cs[ci] += __shfl_xor_sync(0xffffffffu, cs[ci], 16);
                }
                if (lane < 4) {
#pragma unroll
                    for (int nt = 0; nt < 4; ++nt)
#pragma unroll
                        for (int e = 0; e < 2; ++e) {
                            const int ci = nt * 2 + e;
                            const int cg = jj * 128 + wy * 32 + nt * 8 + 2 * lane + e;
                            g_cp[(size_t)(rb * 2 + wx) * N_TOK + cg] = make_float2(cm[ci], cs[ci]);
                        }
                }
            }

            // Row-direction online LSE (MUFU exps, mostly skipped; carried across units)
#pragma unroll
            for (int mt = 0; mt < 4; ++mt)
#pragma unroll
                for (int h = 0; h < 2; ++h) {
                    const int st = mt * 2 + h;
                    float v[8];
#pragma unroll
                    for (int nt = 0; nt < 4; ++nt) {
                        v[nt * 2 + 0] = acc[mt][nt][h * 2 + 0];
                        v[nt * 2 + 1] = acc[mt][nt][h * 2 + 1];
                    }
                    if (jj == rb) {
                        const int row = wx * 64 + mt * 16 + (lane >> 2) + 8 * h;
#pragma unroll
                        for (int nt = 0; nt < 4; ++nt)
#pragma unroll
                            for (int e = 0; e < 2; ++e) {
                                const int col = wy * 32 + nt * 8 + 2 * (lane & 3) + e;
                                if (col == row) sm_p[row] = v[nt * 2 + e];
                            }
                    }
                    float vm = v[0];
#pragma unroll
                    for (int i = 1; i < 8; ++i) vm = fmaxf(vm, v[i]);
                    vm = fmaxf(vm, __shfl_xor_sync(0xffffffffu, vm, 1));
                    vm = fmaxf(vm, __shfl_xor_sync(0xffffffffu, vm, 2));
                    if (__all_sync(0xffffffffu, vm < mst[st] - 2.0f)) continue;
                    const float mnew = fmaxf(mst[st], vm);
                    const float base = k2 * mnew;
                    float sum = expsum8_m(v, k2, base);
                    sum += __shfl_xor_sync(0xffffffffu, sum, 1);
                    sum += __shfl_xor_sync(0xffffffffu, sum, 2);
                    sst[st] = fmaf(sst[st], ex2f(fmaf(mst[st], k2, -base)), sum);
                    mst[st] = mnew;
                }

            // Producer: refill buffer b with tile c+2 once everyone released it.
            if (tid == 0) {
                const int c2 = c + 2;
                if (c2 < ntile) {
                    MBARRIER_WAIT(smbar + 16 + (b << 3), pe[b]); pe[b] ^= 1;
                    const int uu = u0 + (c2 >> 4);
                    const int jj2 = ((uu & 7) << 4) + (c2 & 15);
                    MBARRIER_EXPECT_TX(smbar + (b << 3), TILE_BYTES);
                    CP_BULK(bb[b], g_bfp[1] + (size_t)jj2 * TILE_BYTES, TILE_BYTES,
                            smbar + (b << 3));
                }
            }
        }
    }

    // ---- finalize last run [run_u0, u1) ----
    if ((lane & 3) == 0) {
#pragma unroll
        for (int mt = 0; mt < 4; ++mt)
#pragma unroll
            for (int h = 0; h < 2; ++h) {
                const int row = wx * 64 + mt * 16 + (lane >> 2) + 8 * h;
                sm_m[wy * 128 + row] = mst[mt * 2 + h];
                sm_s[wy * 128 + row] = sst[mt * 2 + h];
            }
    }
    __syncthreads();
    if (tid < 128) {
        float mM = sm_m[tid];
#pragma unroll
        for (int q = 1; q < 4; ++q) mM = fmaxf(mM, sm_m[q * 128 + tid]);
        float sM = 0.0f;
#pragma unroll
        for (int q = 0; q < 4; ++q)
            sM += sm_s[q * 128 + tid] * ex2f(k2 * (sm_m[q * 128 + tid] - mM));
        g_rpu[(size_t)(u1 - 1) * 128 + tid] = make_float2(mM, sM);
        const float2 neutral = make_float2(-1e30f, 0.0f);
        for (int uu = run_u0; uu < u1 - 1; ++uu)
            g_rpu[(size_t)uu * 128 + tid] = neutral;
        const int dchunk = prev_rb >> 4;
        const int clo = run_u0 - (prev_rb << 3), chi = u1 - (prev_rb << 3);
        if (dchunk >= clo && dchunk < chi)
            g_diag[(prev_rb << 7) + tid] = sm_p[tid];
    }
}

__global__ void __launch_bounds__(256) clip_colred(const float* __restrict__ scale_ptr)
{
    const float scale = *scale_ptr;
    const float k2 = scale * 1.4426950408889634f;
    const int c = blockIdx.x * 256 + threadIdx.x;

    float M = -CUDART_INF_F;
#pragma unroll 4
    for (int i = 0; i < 256; ++i) M = fmaxf(M, g_cp[(size_t)i * N_TOK + c].x);
    float S = 0.0f;
#pragma unroll 4
    for (int i = 0; i < 256; ++i) {
        float2 p = g_cp[(size_t)i * N_TOK + c];
        S += p.y * ex2f(k2 * (p.x - M));
    }
    const float d = scale * g_diag[c];
    g_rowloss[N_TOK + c] = 0.69314718055994531f * fmaf(k2, M, __log2f(S)) - d;

    const int rb = c >> 7, lr = c & 127;
    float mM = -CUDART_INF_F;
#pragma unroll
    for (int k = 0; k < 8; ++k) mM = fmaxf(mM, g_rpu[(size_t)(rb * 8 + k) * 128 + lr].x);
    float sM = 0.0f;
#pragma unroll
    for (int k = 0; k < 8; ++k) {
        float2 p = g_rpu[(size_t)(rb * 8 + k) * 128 + lr];
        sM += p.y * ex2f(k2 * (p.x - mM));
    }
    g_rowloss[c] = 0.69314718055994531f * fmaf(k2, mM, __log2f(sM)) - d;
}

__global__ void __launch_bounds__(1024) clip_reduce(float* __restrict__ out)
{
    __shared__ float sm[1024];
    float a = 0.0f;
    const float4* p = (const float4*)g_rowloss;
#pragma unroll 4
    for (int i = threadIdx.x; i < 8192; i += 1024) {
        float4 v = p[i];
        a += (v.x + v.y) + (v.z + v.w);
    }
    sm[threadIdx.x] = a;
    __syncthreads();
    for (int st = 512; st > 0; st >>= 1) {
        if (threadIdx.x < st) sm[threadIdx.x] += sm[threadIdx.x + st];
        __syncthreads();
    }
    if (threadIdx.x == 0) out[0] = sm[0] * (1.0f / 32768.0f);
}

extern "C" void kernel_launch(void* const* d_in, const int* in_sizes, int n_in,
                              void* d_out, int out_size)
{
    (void)in_sizes; (void)n_in; (void)out_size;
    const float* img = (const float*)d_in[0];
    const float* txt = (const float*)d_in[1];
    const float* scl = (const float*)d_in[2];

    cudaFuncSetAttribute(clip_main, cudaFuncAttributeMaxDynamicSharedMemorySize, SMEM_DYN);
    convert_bf16<<<4096, 512>>>(img, txt);
    clip_main<<<NCTA, 256, SMEM_DYN>>>(scl);
    clip_colred<<<64, 256>>>(scl);
    clip_reduce<<<1, 1024>>>((float*)d_out);
}

// round 16
// speedup vs baseline: 1.3121x; 1.0745x over previous
#include <cuda_runtime.h>
#include <cuda_bf16.h>
#include <math_constants.h>

#define N_TOK  16384
#define DIMK   256
#define NCTA   148
#define NUNITS 1024
#define RSTRIDE 528u
#define TILE_BYTES (128u * RSTRIDE)
#define SMEM_DYN (3u * TILE_BYTES)

__device__ __align__(16) unsigned char g_bfp[2][(size_t)N_TOK * RSTRIDE];
__device__ float2 g_cp[256 * N_TOK];
__device__ float2 g_rpu[NUNITS * 128];
__device__ float  g_diag[N_TOK];
__device__ float  g_rowloss[2 * N_TOK];

__device__ __forceinline__ unsigned smem_u32(const void* p) {
    unsigned a;
    asm("{ .reg .u64 t; cvta.to.shared.u64 t, %1; cvt.u32.u64 %0, t; }" : "=r"(a) : "l"(p));
    return a;
}
__device__ __forceinline__ unsigned bf16x2_pack(float lo, float hi) {
    unsigned r;
    asm("cvt.rn.bf16x2.f32 %0, %1, %2;" : "=r"(r) : "f"(hi), "f"(lo));
    return r;
}
__device__ __forceinline__ float ex2f(float x) {
    float y; asm("ex2.approx.ftz.f32 %0, %1;" : "=f"(y) : "f"(x)); return y;
}
__device__ __forceinline__ float expsum8_m(const float* v, float k2, float base) {
    float s0 = 0.f, s1 = 0.f;
#pragma unroll
    for (int i = 0; i < 8; i += 2) {
        s0 += ex2f(fmaf(v[i],     k2, -base));
        s1 += ex2f(fmaf(v[i + 1], k2, -base));
    }
    return s0 + s1;
}

#define MBARRIER_INIT(a, c) \
    asm volatile("mbarrier.init.shared.b64 [%0], %1;" :: "r"((unsigned)(a)), "r"((unsigned)(c)) : "memory")
#define MBARRIER_ARRIVE(a) \
    asm volatile("mbarrier.arrive.shared.b64 _, [%0];" :: "r"((unsigned)(a)) : "memory")
#define MBARRIER_EXPECT_TX(a, tx) \
    asm volatile("mbarrier.arrive.expect_tx.shared.b64 _, [%0], %1;" :: "r"((unsigned)(a)), "r"((unsigned)(tx)) : "memory")
#define MBARRIER_WAIT(a, par) do { \
    unsigned _m = (unsigned)(a), _p = (unsigned)(par), _d; \
    asm volatile("{ .reg .pred p; mbarrier.try_wait.parity.acquire.cta.shared::cta.b64 p, [%1], %2; selp.b32 %0,1,0,p; }" \
        : "=r"(_d) : "r"(_m), "r"(_p) : "memory"); \
    if (!_d) asm volatile("{ .reg .pred P; WL_%=: mbarrier.try_wait.parity.acquire.cta.shared::cta.b64 P, [%0], %1, 0x989680; @P bra.uni WD_%=; bra.uni WL_%=; WD_%=: }" \
        :: "r"(_m), "r"(_p) : "memory"); \
} while (0)
#define CP_BULK(dst, src, sz, mbar) \
    asm volatile("cp.async.bulk.shared::cluster.global.mbarrier::complete_tx::bytes [%0], [%1], %2, [%3];" \
        :: "r"((unsigned)(dst)), "l"(src), "r"((unsigned)(sz)), "r"((unsigned)(mbar)) : "memory")

#define LDSM_X4(d, a) \
    asm volatile("ldmatrix.sync.aligned.m8n8.x4.shared.b16 {%0,%1,%2,%3}, [%4];" \
        : "=r"((d)[0]), "=r"((d)[1]), "=r"((d)[2]), "=r"((d)[3]) : "r"((unsigned)(a)))
#define LDSM_X4T(d, a) \
    asm volatile("ldmatrix.sync.aligned.m8n8.x4.trans.shared.b16 {%0,%1,%2,%3}, [%4];" \
        : "=r"((d)[0]), "=r"((d)[1]), "=r"((d)[2]), "=r"((d)[3]) : "r"((unsigned)(a)))

#define MMA16816(d, a, b0, b1) \
    asm volatile("mma.sync.aligned.m16n8k16.row.col.f32.bf16.bf16.f32 " \
        "{%0,%1,%2,%3}, {%4,%5,%6,%7}, {%8,%9}, {%0,%1,%2,%3};" \
        : "+f"((d)[0]), "+f"((d)[1]), "+f"((d)[2]), "+f"((d)[3]) \
        : "r"((a)[0]), "r"((a)[1]), "r"((a)[2]), "r"((a)[3]), "r"(b0), "r"(b1))

__global__ void __launch_bounds__(512) convert_bf16(const float* __restrict__ img,
                                                    const float* __restrict__ txt)
{
    unsigned t = blockIdx.x * 512u + threadIdx.x;
    const float* src = (t >> 20) ? txt : img;
    unsigned char* dst = g_bfp[t >> 20];
    unsigned i = (t & 0xFFFFFu) << 2;
    unsigned row = i >> 8, col = i & 255u;
    float4 v = *(const float4*)(src + i);
    *(uint2*)(dst + (size_t)row * RSTRIDE + col * 2u) =
        make_uint2(bf16x2_pack(v.x, v.y), bf16x2_pack(v.z, v.w));
}

// ---- deferred epilogue halves (operate on the PREVIOUS tile's accumulators) ----
__device__ __forceinline__ void epi_col(const float (&acc)[4][4][4], int jj, int rb,
                                        float k2, int wx, int wy, int lane)
{
    float cm[8], cs[8];
#pragma unroll
    for (int nt = 0; nt < 4; ++nt)
#pragma unroll
        for (int e = 0; e < 2; ++e) {
            const int ci = nt * 2 + e;
            float v0 = fmaxf(fmaxf(acc[0][nt][e], acc[0][nt][2 + e]),
                             fmaxf(acc[1][nt][e], acc[1][nt][2 + e]));
            float v1 = fmaxf(fmaxf(acc[2][nt][e], acc[2][nt][2 + e]),
                             fmaxf(acc[3][nt][e], acc[3][nt][2 + e]));
            cm[ci] = fmaxf(v0, v1);
        }
#pragma unroll
    for (int ci = 0; ci < 8; ++ci) {
        cm[ci] = fmaxf(cm[ci], __shfl_xor_sync(0xffffffffu, cm[ci], 4));
        cm[ci] = fmaxf(cm[ci], __shfl_xor_sync(0xffffffffu, cm[ci], 8));
        cm[ci] = fmaxf(cm[ci], __shfl_xor_sync(0xffffffffu, cm[ci], 16));
    }
#pragma unroll
    for (int nt = 0; nt < 4; ++nt)
#pragma unroll
        for (int e = 0; e < 2; ++e) {
            const int ci = nt * 2 + e;
            float v[8];
#pragma unroll
            for (int mt = 0; mt < 4; ++mt) {
                v[mt * 2 + 0] = acc[mt][nt][e];
                v[mt * 2 + 1] = acc[mt][nt][2 + e];
            }
            cs[ci] = expsum8_m(v, k2, k2 * cm[ci]);
        }
#pragma unroll
    for (int ci = 0; ci < 8; ++ci) {
        cs[ci] += __shfl_xor_sync(0xffffffffu, cs[ci], 4);
        cs[ci] += __shfl_xor_sync(0xffffffffu, cs[ci], 8);
        cs[ci] += __shfl_xor_sync(0xffffffffu, cs[ci], 16);
    }
    if (lane < 4) {
#pragma unroll
        for (int nt = 0; nt < 4; ++nt)
#pragma unroll
            for (int e = 0; e < 2; ++e) {
                const int ci = nt * 2 + e;
                const int cg = jj * 128 + wy * 32 + nt * 8 + 2 * lane + e;
                g_cp[(size_t)(rb * 2 + wx) * N_TOK + cg] = make_float2(cm[ci], cs[ci]);
            }
    }
}

__device__ __forceinline__ void epi_row(const float (&acc)[4][4][4], int jj, int rb,
                                        float k2, float* mst, float* sst,
                                        float* sm_p, int wx, int wy, int lane)
{
#pragma unroll
    for (int mt = 0; mt < 4; ++mt)
#pragma unroll
        for (int h = 0; h < 2; ++h) {
            const int st = mt * 2 + h;
            float v[8];
#pragma unroll
            for (int nt = 0; nt < 4; ++nt) {
                v[nt * 2 + 0] = acc[mt][nt][h * 2 + 0];
                v[nt * 2 + 1] = acc[mt][nt][h * 2 + 1];
            }
            if (jj == rb) {
                const int row = wx * 64 + mt * 16 + (lane >> 2) + 8 * h;
#pragma unroll
                for (int nt = 0; nt < 4; ++nt)
#pragma unroll
                    for (int e = 0; e < 2; ++e) {
                        const int col = wy * 32 + nt * 8 + 2 * (lane & 3) + e;
                        if (col == row) sm_p[row] = v[nt * 2 + e];
                    }
            }
            float vm = v[0];
#pragma unroll
            for (int i = 1; i < 8; ++i) vm = fmaxf(vm, v[i]);
            vm = fmaxf(vm, __shfl_xor_sync(0xffffffffu, vm, 1));
            vm = fmaxf(vm, __shfl_xor_sync(0xffffffffu, vm, 2));
            if (__all_sync(0xffffffffu, vm < mst[st] - 2.0f)) continue;
            const float mnew = fmaxf(mst[st], vm);
            const float base = k2 * mnew;
            float sum = expsum8_m(v, k2, base);
            sum += __shfl_xor_sync(0xffffffffu, sum, 1);
            sum += __shfl_xor_sync(0xffffffffu, sum, 2);
            sst[st] = fmaf(sst[st], ex2f(fmaf(mst[st], k2, -base)), sum);
            mst[st] = mnew;
        }
}

__device__ __forceinline__ void mma_half(float (&acc)[4][4][4], unsigned bbase,
                                         const unsigned* aAddr, const unsigned* bOff,
                                         int ks0)
{
#pragma unroll
    for (int ks = ks0; ks < ks0 + 8; ++ks) {
        const unsigned ko = (unsigned)ks * 32u;
        unsigned a[4][4];
#pragma unroll
        for (int mt = 0; mt < 4; ++mt) LDSM_X4(a[mt], aAddr[mt] + ko);
#pragma unroll
        for (int nt2 = 0; nt2 < 2; ++nt2) {
            unsigned bf[4];
            LDSM_X4T(bf, bbase + bOff[nt2] + ko);
#pragma unroll
            for (int mt = 0; mt < 4; ++mt) {
                MMA16816(acc[mt][nt2 * 2 + 0], a[mt], bf[0], bf[1]);
                MMA16816(acc[mt][nt2 * 2 + 1], a[mt], bf[2], bf[3]);
            }
        }
    }
}

// Persistent: 148 CTAs x 256 threads; bulk-copy producer on thread 0;
// epilogue deferred one tile behind the MMA (double-buffered accumulators).
__global__ void __launch_bounds__(256, 1)
clip_main(const float* __restrict__ scale_ptr)
{
    extern __shared__ __align__(16) char dsm[];
    __shared__ __align__(8) unsigned long long sh_bar[5];
    __shared__ float sm_m[512], sm_s[512], sm_p[128];

    const int tid = threadIdx.x, wid = tid >> 5, lane = tid & 31;
    const int cta = blockIdx.x;
    const int u0 = (cta * NUNITS) / NCTA;
    const int u1 = ((cta + 1) * NUNITS) / NCTA;
    const int ntile = (u1 - u0) * 16;

    const unsigned abase = smem_u32(dsm);
    const unsigned bb[2] = { abase + TILE_BYTES, abase + 2u * TILE_BYTES };
    const unsigned smbar = smem_u32(sh_bar);

    if (tid == 0) {
        MBARRIER_INIT(smbar + 0, 1);    MBARRIER_INIT(smbar + 8, 1);
        MBARRIER_INIT(smbar + 16, 256); MBARRIER_INIT(smbar + 24, 256);
        MBARRIER_INIT(smbar + 32, 1);
    }
    __syncthreads();

    const float scale = *scale_ptr;
    const float k2 = scale * 1.4426950408889634f;

    if (tid == 0) {
#pragma unroll
        for (int cpr = 0; cpr < 2; ++cpr) {
            const int jj = ((u0 & 7) << 4) + cpr;
            MBARRIER_EXPECT_TX(smbar + (cpr << 3), TILE_BYTES);
            CP_BULK(bb[cpr], g_bfp[1] + (size_t)jj * TILE_BYTES, TILE_BYTES, smbar + (cpr << 3));
        }
    }

    const int wx = wid & 1, wy = wid >> 1;
    unsigned aAddr[4];
#pragma unroll
    for (int mt = 0; mt < 4; ++mt) {
        unsigned row = (unsigned)(wx * 64 + mt * 16 + (lane & 7) + ((lane >> 3) & 1) * 8);
        aAddr[mt] = abase + row * RSTRIDE + (unsigned)(lane >> 4) * 16u;
    }
    unsigned bOff[2];
#pragma unroll
    for (int nt2 = 0; nt2 < 2; ++nt2) {
        unsigned row = (unsigned)(wy * 32 + nt2 * 16 + (lane & 7) + ((lane >> 4) & 1) * 8);
        bOff[nt2] = row * RSTRIDE + (unsigned)((lane >> 3) & 1) * 16u;
    }

    float acc0[4][4][4], acc1[4][4][4];
    float mst[8], sst[8];
#pragma unroll
    for (int i = 0; i < 8; ++i) { mst[i] = -1e30f; sst[i] = 0.0f; }

    int c = 0, pf[2] = {0, 0}, pe[2] = {0, 0}, pa = 0;
    int prev_rb = -1, run_u0 = u0;
    int pend_jj = 0, pend_rb = 0;
    bool haspend = false;

    for (int u = u0; u < u1; ++u) {
        const int rb = u >> 3, chunk = u & 7;
        if (rb != prev_rb) {
            if (prev_rb >= 0) {
                // drain pending epilogue (tile c-1, odd -> buffer acc1)
                if (haspend) {
                    epi_col(acc1, pend_jj, pend_rb, k2, wx, wy, lane);
                    epi_row(acc1, pend_jj, pend_rb, k2, mst, sst, sm_p, wx, wy, lane);
                    haspend = false;
                }
                if ((lane & 3) == 0) {
#pragma unroll
                    for (int mt = 0; mt < 4; ++mt)
#pragma unroll
                        for (int h = 0; h < 2; ++h) {
                            const int row = wx * 64 + mt * 16 + (lane >> 2) + 8 * h;
                            sm_m[wy * 128 + row] = mst[mt * 2 + h];
                            sm_s[wy * 128 + row] = sst[mt * 2 + h];
                        }
                }
                __syncthreads();
                if (tid < 128) {
                    float mM = sm_m[tid];
#pragma unroll
                    for (int q = 1; q < 4; ++q) mM = fmaxf(mM, sm_m[q * 128 + tid]);
                    float sM = 0.0f;
#pragma unroll
                    for (int q = 0; q < 4; ++q)
                        sM += sm_s[q * 128 + tid] * ex2f(k2 * (sm_m[q * 128 + tid] - mM));
                    g_rpu[(size_t)(u - 1) * 128 + tid] = make_float2(mM, sM);
                    const float2 neutral = make_float2(-1e30f, 0.0f);
                    for (int uu = run_u0; uu < u - 1; ++uu)
                        g_rpu[(size_t)uu * 128 + tid] = neutral;
                    const int dchunk = prev_rb >> 4;
                    const int clo = run_u0 - (prev_rb << 3), chi = u - (prev_rb << 3);
                    if (dchunk >= clo && dchunk < chi)
                        g_diag[(prev_rb << 7) + tid] = sm_p[tid];
                }
                __syncthreads();
#pragma unroll
                for (int i = 0; i < 8; ++i) { mst[i] = -1e30f; sst[i] = 0.0f; }
                run_u0 = u;
            }
            __syncthreads();
            if (tid == 0) {
                MBARRIER_EXPECT_TX(smbar + 32, TILE_BYTES);
                CP_BULK(abase, g_bfp[0] + (size_t)rb * TILE_BYTES, TILE_BYTES, smbar + 32);
            }
            MBARRIER_WAIT(smbar + 32, pa); pa ^= 1;
            prev_rb = rb;
        }

        // 16 tiles as 8 even/odd pairs (buffer parity compile-time).
        for (int t2 = 0; t2 < 8; ++t2) {
            // ---- even tile: acc0 current, acc1 pending ----
            {
                const int jj = (chunk << 4) + t2 * 2;
                MBARRIER_WAIT(smbar + 0, pf[0]); pf[0] ^= 1;
#pragma unroll
                for (int mt = 0; mt < 4; ++mt)
#pragma unroll
                    for (int nt = 0; nt < 4; ++nt)
#pragma unroll
                        for (int e = 0; e < 4; ++e) acc0[mt][nt][e] = 0.0f;
                mma_half(acc0, bb[0], aAddr, bOff, 0);
                if (haspend) epi_col(acc1, pend_jj, pend_rb, k2, wx, wy, lane);
                mma_half(acc0, bb[0], aAddr, bOff, 8);
                if (haspend) epi_row(acc1, pend_jj, pend_rb, k2, mst, sst, sm_p, wx, wy, lane);
                MBARRIER_ARRIVE(smbar + 16);
                if (tid == 0) {
                    const int c2 = c + 2;
                    if (c2 < ntile) {
                        MBARRIER_WAIT(smbar + 16, pe[0]); pe[0] ^= 1;
                        const int uu = u0 + (c2 >> 4);
                        const int jj2 = ((uu & 7) << 4) + (c2 & 15);
                        MBARRIER_EXPECT_TX(smbar + 0, TILE_BYTES);
                        CP_BULK(bb[0], g_bfp[1] + (size_t)jj2 * TILE_BYTES, TILE_BYTES, smbar + 0);
                    }
                }
                pend_jj = jj; pend_rb = rb; haspend = true;
                ++c;
            }
            // ---- odd tile: acc1 current, acc0 pending ----
            {
                const int jj = (chunk << 4) + t2 * 2 + 1;
                MBARRIER_WAIT(smbar + 8, pf[1]); pf[1] ^= 1;
#pragma unroll
                for (int mt = 0; mt < 4; ++mt)
#pragma unroll
                    for (int nt = 0; nt < 4; ++nt)
#pragma unroll
                        for (int e = 0; e < 4; ++e) acc1[mt][nt][e] = 0.0f;
                mma_half(acc1, bb[1], aAddr, bOff, 0);
                epi_col(acc0, pend_jj, pend_rb, k2, wx, wy, lane);
                mma_half(acc1, bb[1], aAddr, bOff, 8);
                epi_row(acc0, pend_jj, pend_rb, k2, mst, sst, sm_p, wx, wy, lane);
                MBARRIER_ARRIVE(smbar + 24);
                if (tid == 0) {
                    const int c2 = c + 2;
                    if (c2 < ntile) {
                        MBARRIER_WAIT(smbar + 24, pe[1]); pe[1] ^= 1;
                        const int uu = u0 + (c2 >> 4);
                        const int jj2 = ((uu & 7) << 4) + (c2 & 15);
                        MBARRIER_EXPECT_TX(smbar + 8, TILE_BYTES);
                        CP_BULK(bb[1], g_bfp[1] + (size_t)jj2 * TILE_BYTES, TILE_BYTES, smbar + 8);
                    }
                }
                pend_jj = jj; pend_rb = rb;
                ++c;
            }
        }
    }

    // drain final pending (odd tile -> acc1)
    if (haspend) {
        epi_col(acc1, pend_jj, pend_rb, k2, wx, wy, lane);
        epi_row(acc1, pend_jj, pend_rb, k2, mst, sst, sm_p, wx, wy, lane);
    }
    if ((lane & 3) == 0) {
#pragma unroll
        for (int mt = 0; mt < 4; ++mt)
#pragma unroll
            for (int h = 0; h < 2; ++h) {
                const int row = wx * 64 + mt * 16 + (lane >> 2) + 8 * h;
                sm_m[wy * 128 + row] = mst[mt * 2 + h];
                sm_s[wy * 128 + row] = sst[mt * 2 + h];
            }
    }
    __syncthreads();
    if (tid < 128) {
        float mM = sm_m[tid];
#pragma unroll
        for (int q = 1; q < 4; ++q) mM = fmaxf(mM, sm_m[q * 128 + tid]);
        float sM = 0.0f;
#pragma unroll
        for (int q = 0; q < 4; ++q)
            sM += sm_s[q * 128 + tid] * ex2f(k2 * (sm_m[q * 128 + tid] - mM));
        g_rpu[(size_t)(u1 - 1) * 128 + tid] = make_float2(mM, sM);
        const float2 neutral = make_float2(-1e30f, 0.0f);
        for (int uu = run_u0; uu < u1 - 1; ++uu)
            g_rpu[(size_t)uu * 128 + tid] = neutral;
        const int dchunk = prev_rb >> 4;
        const int clo = run_u0 - (prev_rb << 3), chi = u1 - (prev_rb << 3);
        if (dchunk >= clo && dchunk < chi)
            g_diag[(prev_rb << 7) + tid] = sm_p[tid];
    }
}

__global__ void __launch_bounds__(256) clip_colred(const float* __restrict__ scale_ptr)
{
    const float scale = *scale_ptr;
    const float k2 = scale * 1.4426950408889634f;
    const int c = blockIdx.x * 256 + threadIdx.x;

    float M = -CUDART_INF_F;
#pragma unroll 4
    for (int i = 0; i < 256; ++i) M = fmaxf(M, g_cp[(size_t)i * N_TOK + c].x);
    float S = 0.0f;
#pragma unroll 4
    for (int i = 0; i < 256; ++i) {
        float2 p = g_cp[(size_t)i * N_TOK + c];
        S += p.y * ex2f(k2 * (p.x - M));
    }
    const float d = scale * g_diag[c];
    g_rowloss[N_TOK + c] = 0.69314718055994531f * fmaf(k2, M, __log2f(S)) - d;

    const int rb = c >> 7, lr = c & 127;
    float mM = -CUDART_INF_F;
#pragma unroll
    for (int k = 0; k < 8; ++k) mM = fmaxf(mM, g_rpu[(size_t)(rb * 8 + k) * 128 + lr].x);
    float sM = 0.0f;
#pragma unroll
    for (int k = 0; k < 8; ++k) {
        float2 p = g_rpu[(size_t)(rb * 8 + k) * 128 + lr];
        sM += p.y * ex2f(k2 * (p.x - mM));
    }
    g_rowloss[c] = 0.69314718055994531f * fmaf(k2, mM, __log2f(sM)) - d;
}

__global__ void __launch_bounds__(1024) clip_reduce(float* __restrict__ out)
{
    __shared__ float sm[1024];
    float a = 0.0f;
    const float4* p = (const float4*)g_rowloss;
#pragma unroll 4
    for (int i = threadIdx.x; i < 8192; i += 1024) {
        float4 v = p[i];
        a += (v.x + v.y) + (v.z + v.w);
    }
    sm[threadIdx.x] = a;
    __syncthreads();
    for (int st = 512; st > 0; st >>= 1) {
        if (threadIdx.x < st) sm[threadIdx.x] += sm[threadIdx.x + st];
        __syncthreads();
    }
    if (threadIdx.x == 0) out[0] = sm[0] * (1.0f / 32768.0f);
}

extern "C" void kernel_launch(void* const* d_in, const int* in_sizes, int n_in,
                              void* d_out, int out_size)
{
    (void)in_sizes; (void)n_in; (void)out_size;
    const float* img = (const float*)d_in[0];
    const float* txt = (const float*)d_in[1];
    const float* scl = (const float*)d_in[2];

    cudaFuncSetAttribute(clip_main, cudaFuncAttributeMaxDynamicSharedMemorySize, SMEM_DYN);
    convert_bf16<<<4096, 512>>>(img, txt);
    clip_main<<<NCTA, 256, SMEM_DYN>>>(scl);
    clip_colred<<<64, 256>>>(scl);
    clip_reduce<<<1, 1024>>>((float*)d_out);
}